// round 1
// baseline (speedup 1.0000x reference)
#include <cuda_runtime.h>

#define BB 8
#define TT 2048
#define BT 16384
#define DD 512
#define KK 1024
#define HALF_N 8388608u   // BT*KK/2

// ---------------- scratch (static device allocations only) ----------------
__device__ float g_h1[BT * 256];
__device__ float g_res[BT * DD];
__device__ float g_qout[BT * DD];
__device__ unsigned long long g_best[BT];
__device__ float g_csq[KK];
__device__ float g_acc[2];   // [0]=commit sum, [1]=mse sum

// ---------------- JAX threefry2x32 (exact) ----------------
__host__ __device__ inline void tf2x32(unsigned k0, unsigned k1,
                                       unsigned x0, unsigned x1,
                                       unsigned& o0, unsigned& o1) {
    unsigned ks2 = k0 ^ k1 ^ 0x1BD11BDAu;
    x0 += k0; x1 += k1;
#define TF_RND(r) { x0 += x1; x1 = (x1 << (r)) | (x1 >> (32 - (r))); x1 ^= x0; }
    TF_RND(13) TF_RND(15) TF_RND(26) TF_RND(6)
    x0 += k1;  x1 += ks2 + 1u;
    TF_RND(17) TF_RND(29) TF_RND(16) TF_RND(24)
    x0 += ks2; x1 += k0 + 2u;
    TF_RND(13) TF_RND(15) TF_RND(26) TF_RND(6)
    x0 += k0;  x1 += k1 + 3u;
    TF_RND(17) TF_RND(29) TF_RND(16) TF_RND(24)
    x0 += k1;  x1 += ks2 + 4u;
    TF_RND(13) TF_RND(15) TF_RND(26) TF_RND(6)
    x0 += ks2; x1 += k0 + 5u;
#undef TF_RND
    o0 = x0; o1 = x1;
}

__device__ inline float gumbel_from_bits(unsigned bits) {
    // uniform in [tiny, 1): bitcast((bits>>9)|0x3f800000) - 1, clamp 0 -> tiny
    float f = __uint_as_float((bits >> 9) | 0x3f800000u) - 1.0f;
    float u = (f == 0.0f) ? 1.17549435e-38f : f;
    return -__logf(-__logf(u));
}

__device__ inline unsigned fmap(float f) {   // monotone float -> uint
    unsigned u = __float_as_uint(f);
    return (u & 0x80000000u) ? ~u : (u | 0x80000000u);
}

__device__ inline float gelu_exact(float v) {
    return 0.5f * v * (1.0f + erff(v * 0.7071067811865476f));
}

// ---------------- generic conv3 (same-pad, per-batch halo) as tiled GEMM ----
// in:[BT,CIN]  w:[COUT,CIN,3]  out:[BT,COUT]
template<int CIN, int COUT, bool FUSE_MSE>
__global__ void __launch_bounds__(256) conv3(
    const float* __restrict__ in, const float* __restrict__ w,
    const float* __restrict__ bias, float* __restrict__ out,
    const float* __restrict__ xref)
{
    __shared__ float As[16][129];
    __shared__ float Bs[16][129];
    const int tid = threadIdx.x;
    const int tx = tid & 15, ty = tid >> 4;
    const int r0 = blockIdx.x * 128;
    const int n0 = blockIdx.y * 128;
    const int lk = tid & 15, lm = tid >> 4;

    float acc[8][8];
#pragma unroll
    for (int i = 0; i < 8; ++i)
#pragma unroll
        for (int j = 0; j < 8; ++j) acc[i][j] = 0.0f;

    for (int tap = 0; tap < 3; ++tap) {
        for (int cc = 0; cc < CIN; cc += 16) {
#pragma unroll
            for (int l = 0; l < 8; ++l) {
                int m = lm + 16 * l;
                int r = r0 + m;
                int t = r & (TT - 1);
                int st = t + tap - 1;
                int ci = cc + lk;
                float v = 0.0f;
                if (st >= 0 && st < TT && ci < CIN)
                    v = in[(r + tap - 1) * CIN + ci];
                As[lk][m] = v;
            }
#pragma unroll
            for (int l = 0; l < 8; ++l) {
                int n = lm + 16 * l;
                int co = n0 + n;
                int ci = cc + lk;
                float v = 0.0f;
                if (co < COUT && ci < CIN)
                    v = w[(co * CIN + ci) * 3 + tap];
                Bs[lk][n] = v;
            }
            __syncthreads();
#pragma unroll
            for (int kk = 0; kk < 16; ++kk) {
                float a[8], b[8];
#pragma unroll
                for (int i = 0; i < 8; ++i) a[i] = As[kk][ty + 16 * i];
#pragma unroll
                for (int j = 0; j < 8; ++j) b[j] = Bs[kk][tx + 16 * j];
#pragma unroll
                for (int i = 0; i < 8; ++i)
#pragma unroll
                    for (int j = 0; j < 8; ++j)
                        acc[i][j] = fmaf(a[i], b[j], acc[i][j]);
            }
            __syncthreads();
        }
    }

    float local = 0.0f;
#pragma unroll
    for (int i = 0; i < 8; ++i) {
        int r = r0 + ty + 16 * i;
#pragma unroll
        for (int j = 0; j < 8; ++j) {
            int co = n0 + tx + 16 * j;
            if (co < COUT) {
                float v = gelu_exact(acc[i][j] + bias[co]);
                if (FUSE_MSE) {
                    float d = xref[r * COUT + co] - v;
                    local += d * d;
                } else {
                    out[r * COUT + co] = v;
                }
            }
        }
    }
    if (FUSE_MSE) {
        __shared__ float red[256];
        red[tid] = local;
        __syncthreads();
        for (int s = 128; s > 0; s >>= 1) {
            if (tid < s) red[tid] += red[tid + s];
            __syncthreads();
        }
        if (tid == 0) atomicAdd(&g_acc[1], red[0]);
    }
}

// ---------------- VQ score GEMM + gumbel + fused argmax ----------------
// block: 64 lower-half rows [r0,r0+64) + their threefry partners [r0+8192, ...)
// cols: 128 codes. Pairing halves threefry work.
__global__ void __launch_bounds__(256) vq_score(
    const float* __restrict__ cb, unsigned fk0, unsigned fk1)
{
    __shared__ float As[16][129];
    __shared__ float Bs[16][129];
    __shared__ unsigned long long sbest[128];
    const int tid = threadIdx.x;
    const int tx = tid & 15, ty = tid >> 4;
    const int r0 = blockIdx.x * 64;
    const int k0 = blockIdx.y * 128;
    const int lk = tid & 15, lm = tid >> 4;

    if (tid < 128) sbest[tid] = 0ull;

    float acc[8][8];
#pragma unroll
    for (int i = 0; i < 8; ++i)
#pragma unroll
        for (int j = 0; j < 8; ++j) acc[i][j] = 0.0f;

    for (int cc = 0; cc < DD; cc += 16) {
#pragma unroll
        for (int l = 0; l < 8; ++l) {
            int m = lm + 16 * l;
            int r = (m < 64) ? (r0 + m) : (8192 + r0 + (m - 64));
            As[lk][m] = g_res[r * DD + cc + lk];
        }
#pragma unroll
        for (int l = 0; l < 8; ++l) {
            int n = lm + 16 * l;
            Bs[lk][n] = cb[(k0 + n) * DD + cc + lk];
        }
        __syncthreads();
#pragma unroll
        for (int kk = 0; kk < 16; ++kk) {
            float a[8], b[8];
#pragma unroll
            for (int i = 0; i < 8; ++i) a[i] = As[kk][ty + 16 * i];
#pragma unroll
            for (int j = 0; j < 8; ++j) b[j] = Bs[kk][tx + 16 * j];
#pragma unroll
            for (int i = 0; i < 8; ++i)
#pragma unroll
                for (int j = 0; j < 8; ++j)
                    acc[i][j] = fmaf(a[i], b[j], acc[i][j]);
        }
        __syncthreads();
    }

    // epilogue: rows i (lower) pair with i+4 (upper half, +8192)
#pragma unroll
    for (int i = 0; i < 4; ++i) {
        int mL = ty + 16 * i;          // 0..63
        unsigned btL = (unsigned)(r0 + mL);
#pragma unroll
        for (int j = 0; j < 8; ++j) {
            int k = k0 + tx + 16 * j;
            unsigned n = btL * 1024u + (unsigned)k;   // < HALF_N always
            unsigned b0, b1;
            tf2x32(fk0, fk1, n, n + HALF_N, b0, b1);
            float g0 = gumbel_from_bits(b0);
            float g1 = gumbel_from_bits(b1);
            float csq = g_csq[k];
            float sL = (2.0f * acc[i][j]     - csq) / 0.1f + g0;
            float sH = (2.0f * acc[i + 4][j] - csq) / 0.1f + g1;
            unsigned long long low = (unsigned long long)(~(unsigned)k);
            atomicMax(&sbest[mL],      ((unsigned long long)fmap(sL) << 32) | low);
            atomicMax(&sbest[64 + mL], ((unsigned long long)fmap(sH) << 32) | low);
        }
    }
    __syncthreads();
    if (tid < 128) {
        int r = (tid < 64) ? (r0 + tid) : (8192 + r0 + (tid - 64));
        atomicMax(&g_best[r], sbest[tid]);
    }
}

// ---------------- VQ update: gather, q_out accum, residual, commit loss ----
__global__ void vq_update(const float* __restrict__ cb, int stage) {
    int bt = blockIdx.x;
    int tid = threadIdx.x;  // 128
    unsigned kinv = (unsigned)(g_best[bt] & 0xffffffffull);
    int k = (int)(~kinv);
    float local = 0.0f;
#pragma unroll
    for (int l = 0; l < 4; ++l) {
        int d = tid + 128 * l;
        float r = g_res[bt * DD + d];
        float q = cb[k * DD + d];
        float diff = q - r;
        float qst = r + diff;                     // straight-through value
        float qo = (stage == 0) ? qst : (g_qout[bt * DD + d] + qst);
        g_qout[bt * DD + d] = qo;
        g_res[bt * DD + d] = r - q;
        local += diff * diff;
    }
    __shared__ float red[128];
    red[tid] = local;
    __syncthreads();
    for (int s = 64; s > 0; s >>= 1) {
        if (tid < s) red[tid] += red[tid + s];
        __syncthreads();
    }
    if (tid == 0) atomicAdd(&g_acc[0], red[0]);
}

// ---------------- init: codebook squared norms + zero accumulators ----------
__global__ void vq_init(const float* __restrict__ cb) {
    int k = blockIdx.x;
    int tid = threadIdx.x;  // 128
    float local = 0.0f;
#pragma unroll
    for (int l = 0; l < 4; ++l) {
        float c = cb[k * DD + tid + 128 * l];
        local += c * c;
    }
    __shared__ float red[128];
    red[tid] = local;
    __syncthreads();
    for (int s = 64; s > 0; s >>= 1) {
        if (tid < s) red[tid] += red[tid + s];
        __syncthreads();
    }
    if (tid == 0) g_csq[k] = red[0];
    if (blockIdx.x == 0 && tid < 2) g_acc[tid] = 0.0f;
}

__global__ void zero_best() {
    g_best[blockIdx.x * 256 + threadIdx.x] = 0ull;
}

__global__ void finalize_k(float* __restrict__ out) {
    out[0] = g_acc[1] * (1.0f / 1638400.0f)      // mse: /(BT*100)
           + g_acc[0] * (1.0f / 67108864.0f);    // commit: /(8 stages * BT * 512)
}

// ---------------- host launcher (graph-capturable, alloc-free) -------------
extern "C" void kernel_launch(void* const* d_in, const int* in_sizes, int n_in,
                              void* d_out, int out_size) {
    const float* x   = (const float*)d_in[0];
    const float* ew1 = (const float*)d_in[1];
    const float* eb1 = (const float*)d_in[2];
    const float* ew2 = (const float*)d_in[3];
    const float* eb2 = (const float*)d_in[4];
    const float* cb  = (const float*)d_in[5];
    const float* dw1 = (const float*)d_in[6];
    const float* db1 = (const float*)d_in[7];
    const float* dw2 = (const float*)d_in[8];
    const float* db2 = (const float*)d_in[9];
    float* out = (float*)d_out;

    float *h1, *res, *qout;
    cudaGetSymbolAddress((void**)&h1,   g_h1);
    cudaGetSymbolAddress((void**)&res,  g_res);
    cudaGetSymbolAddress((void**)&qout, g_qout);

    // fold-in keys for each VQ stage: threefry((0,42),(0,i))
    unsigned fk0[8], fk1[8];
    for (int s = 0; s < 8; ++s) tf2x32(0u, 42u, 0u, (unsigned)s, fk0[s], fk1[s]);

    vq_init<<<KK, 128>>>(cb);

    // encoder
    conv3<100, 256, false><<<dim3(128, 2), 256>>>(x,  ew1, eb1, h1,  nullptr);
    conv3<256, 512, false><<<dim3(128, 4), 256>>>(h1, ew2, eb2, res, nullptr);

    // residual VQ, 8 stages
    for (int s = 0; s < 8; ++s) {
        zero_best<<<64, 256>>>();
        vq_score<<<dim3(128, 8), 256>>>(cb, fk0[s], fk1[s]);
        vq_update<<<BT, 128>>>(cb, s);
    }

    // decoder (+ fused MSE on the last conv)
    conv3<512, 256, false><<<dim3(128, 2), 256>>>(qout, dw1, db1, h1, nullptr);
    conv3<256, 100, true ><<<dim3(128, 1), 256>>>(h1,  dw2, db2, nullptr, x);

    finalize_k<<<1, 1>>>(out);
}

// round 2
// speedup vs baseline: 1.2608x; 1.2608x over previous
#include <cuda_runtime.h>

#define BB 8
#define TT 2048
#define BT 16384
#define DD 512
#define KK 1024
#define HALF_N 8388608u   // BT*KK/2

// ---------------- scratch (static device allocations only) ----------------
__device__ float g_h1[BT * 256];
__device__ float g_res[BT * DD];
__device__ float g_qout[BT * DD];
__device__ float g_cbT[DD * KK];          // codebook transposed [d][k]
__device__ unsigned long long g_best[BT];
__device__ float g_csq[KK];
__device__ float g_acc[2];   // [0]=commit sum, [1]=mse sum

// ---------------- packed f32x2 helpers ----------------
__device__ __forceinline__ void splat2(unsigned long long& d, float a) {
    asm("mov.b64 %0, {%1, %1};" : "=l"(d) : "f"(a));
}
__device__ __forceinline__ void pack2(unsigned long long& d, float a, float b) {
    asm("mov.b64 %0, {%1, %2};" : "=l"(d) : "f"(a), "f"(b));
}
__device__ __forceinline__ void unpack2(float& a, float& b, unsigned long long d) {
    asm("mov.b64 {%0, %1}, %2;" : "=f"(a), "=f"(b) : "l"(d));
}
__device__ __forceinline__ void ffma2(unsigned long long& acc,
                                      unsigned long long a, unsigned long long b) {
    asm("fma.rn.f32x2 %0, %1, %2, %0;" : "+l"(acc) : "l"(a), "l"(b));
}

// ---------------- JAX threefry2x32 (exact) ----------------
__host__ __device__ inline void tf2x32(unsigned k0, unsigned k1,
                                       unsigned x0, unsigned x1,
                                       unsigned& o0, unsigned& o1) {
    unsigned ks2 = k0 ^ k1 ^ 0x1BD11BDAu;
    x0 += k0; x1 += k1;
#define TF_RND(r) { x0 += x1; x1 = (x1 << (r)) | (x1 >> (32 - (r))); x1 ^= x0; }
    TF_RND(13) TF_RND(15) TF_RND(26) TF_RND(6)
    x0 += k1;  x1 += ks2 + 1u;
    TF_RND(17) TF_RND(29) TF_RND(16) TF_RND(24)
    x0 += ks2; x1 += k0 + 2u;
    TF_RND(13) TF_RND(15) TF_RND(26) TF_RND(6)
    x0 += k0;  x1 += k1 + 3u;
    TF_RND(17) TF_RND(29) TF_RND(16) TF_RND(24)
    x0 += k1;  x1 += ks2 + 4u;
    TF_RND(13) TF_RND(15) TF_RND(26) TF_RND(6)
    x0 += ks2; x1 += k0 + 5u;
#undef TF_RND
    o0 = x0; o1 = x1;
}

__device__ inline float gumbel_from_bits(unsigned bits) {
    float f = __uint_as_float((bits >> 9) | 0x3f800000u) - 1.0f;
    float u = (f == 0.0f) ? 1.17549435e-38f : f;
    return -__logf(-__logf(u));
}

__device__ inline unsigned fmap(float f) {   // monotone float -> uint
    unsigned u = __float_as_uint(f);
    return (u & 0x80000000u) ? ~u : (u | 0x80000000u);
}

__device__ inline float gelu_exact(float v) {
    return 0.5f * v * (1.0f + erff(v * 0.7071067811865476f));
}

// ---------------- codebook transpose: cbT[d][k] = cb[k][d] ----------------
__global__ void transpose_cb(const float* __restrict__ cb) {
    __shared__ float t[32][33];
    int k0 = blockIdx.x * 32;
    int d0 = blockIdx.y * 32;
    int tx = threadIdx.x, ty = threadIdx.y;  // 32 x 8
    for (int l = 0; l < 32; l += 8)
        t[ty + l][tx] = cb[(k0 + ty + l) * DD + d0 + tx];
    __syncthreads();
    for (int l = 0; l < 32; l += 8)
        g_cbT[(d0 + ty + l) * KK + k0 + tx] = t[tx][ty + l];
}

// ---------------- generic conv3 (same-pad, per-batch halo), FFMA2 core ----
// in:[BT,CIN]  w:[COUT,CIN,3]  out:[BT,COUT]
template<int CIN, int COUT, bool FUSE_MSE>
__global__ void __launch_bounds__(256) conv3(
    const float* __restrict__ in, const float* __restrict__ w,
    const float* __restrict__ bias, float* __restrict__ out,
    const float* __restrict__ xref)
{
    __shared__ float As[16][129];
    __shared__ float Bs[16][129];
    const int tid = threadIdx.x;
    const int tx = tid & 15, ty = tid >> 4;
    const int r0 = blockIdx.x * 128;
    const int n0 = blockIdx.y * 128;
    const int lk = tid & 15, lm = tid >> 4;

    unsigned long long acc2[8][4];
#pragma unroll
    for (int i = 0; i < 8; ++i)
#pragma unroll
        for (int j = 0; j < 4; ++j) acc2[i][j] = 0ull;

    for (int tap = 0; tap < 3; ++tap) {
        for (int cc = 0; cc < CIN; cc += 16) {
#pragma unroll
            for (int l = 0; l < 8; ++l) {
                int m = lm + 16 * l;
                int r = r0 + m;
                int t = r & (TT - 1);
                int st = t + tap - 1;
                int ci = cc + lk;
                float v = 0.0f;
                if (st >= 0 && st < TT && ci < CIN)
                    v = in[(r + tap - 1) * CIN + ci];
                As[lk][m] = v;
            }
#pragma unroll
            for (int l = 0; l < 8; ++l) {
                int n = lm + 16 * l;
                int co = n0 + n;
                int ci = cc + lk;
                float v = 0.0f;
                if (co < COUT && ci < CIN)
                    v = w[(co * CIN + ci) * 3 + tap];
                Bs[lk][n] = v;
            }
            __syncthreads();
#pragma unroll
            for (int kk = 0; kk < 16; ++kk) {
                float a[8], b[8];
#pragma unroll
                for (int i = 0; i < 8; ++i) a[i] = As[kk][ty + 16 * i];
#pragma unroll
                for (int j = 0; j < 8; ++j) b[j] = Bs[kk][tx + 16 * j];
                unsigned long long b2[4], a2;
#pragma unroll
                for (int j = 0; j < 4; ++j) pack2(b2[j], b[2 * j], b[2 * j + 1]);
#pragma unroll
                for (int i = 0; i < 8; ++i) {
                    splat2(a2, a[i]);
#pragma unroll
                    for (int j = 0; j < 4; ++j) ffma2(acc2[i][j], a2, b2[j]);
                }
            }
            __syncthreads();
        }
    }

    float local = 0.0f;
#pragma unroll
    for (int i = 0; i < 8; ++i) {
        int r = r0 + ty + 16 * i;
#pragma unroll
        for (int jp = 0; jp < 4; ++jp) {
            float v0, v1;
            unpack2(v0, v1, acc2[i][jp]);
            float vv[2] = {v0, v1};
#pragma unroll
            for (int h = 0; h < 2; ++h) {
                int j = 2 * jp + h;
                int co = n0 + tx + 16 * j;
                if (co < COUT) {
                    float v = gelu_exact(vv[h] + bias[co]);
                    if (FUSE_MSE) {
                        float d = xref[r * COUT + co] - v;
                        local += d * d;
                    } else {
                        out[r * COUT + co] = v;
                    }
                }
            }
        }
    }
    if (FUSE_MSE) {
        __shared__ float red[256];
        red[tid] = local;
        __syncthreads();
        for (int s = 128; s > 0; s >>= 1) {
            if (tid < s) red[tid] += red[tid + s];
            __syncthreads();
        }
        if (tid == 0) atomicAdd(&g_acc[1], red[0]);
    }
}

// ---------------- VQ score GEMM (float4 + FFMA2) + gumbel + fused argmax ----
// Block tile: rows = 64 lower-half bt [r0,r0+64) at m=0..63, plus their threefry
// partners [8192+r0, ...) at m=64..127.  Cols = 128 codes [k0, k0+128).
// Thread (tx,ty): rows ty*4+{0..3} (low) & 64+ty*4+{0..3} (high),
//                 cols tx*4+{0..3} & 64+tx*4+{0..3}.
#define SAS 136   // smem row stride in floats (544B, 16B aligned)
__global__ void __launch_bounds__(256) vq_score(
    unsigned fk0, unsigned fk1)
{
    __shared__ __align__(16) float As[16][SAS];
    __shared__ __align__(16) float Bs[16][SAS];
    __shared__ unsigned long long sbest[128];
    const int tid = threadIdx.x;
    const int tx = tid & 15, ty = tid >> 4;
    const int r0 = blockIdx.x * 64;
    const int k0 = blockIdx.y * 128;

    if (tid < 128) sbest[tid] = 0ull;

    // staging maps
    const int sm  = tid >> 1;            // A: row m 0..127
    const int skq = tid & 1;             // A: k-chunk (8 k's each)
    const int arow = (sm < 64) ? (r0 + sm) : (8192 + r0 + (sm - 64));
    const float* aptr = &g_res[(size_t)arow * DD];
    const int bk  = tid >> 4;            // B: k row 0..15
    const int bn4 = (tid & 15) * 4;      // B: n offset

    unsigned long long acc2[8][4];
#pragma unroll
    for (int i = 0; i < 8; ++i)
#pragma unroll
        for (int j = 0; j < 4; ++j) acc2[i][j] = 0ull;

    for (int cc = 0; cc < DD; cc += 16) {
        // A: [16 k][128 m] from g_res (k contiguous in source)
        float4 av0 = *(const float4*)(aptr + cc + 8 * skq);
        float4 av1 = *(const float4*)(aptr + cc + 8 * skq + 4);
        As[8 * skq + 0][sm] = av0.x;
        As[8 * skq + 1][sm] = av0.y;
        As[8 * skq + 2][sm] = av0.z;
        As[8 * skq + 3][sm] = av0.w;
        As[8 * skq + 4][sm] = av1.x;
        As[8 * skq + 5][sm] = av1.y;
        As[8 * skq + 6][sm] = av1.z;
        As[8 * skq + 7][sm] = av1.w;
        // B: [16 k][128 n] from g_cbT (n contiguous in source)
        const float* bptr = &g_cbT[(size_t)(cc + bk) * KK + k0];
        *(float4*)&Bs[bk][bn4]      = *(const float4*)(bptr + bn4);
        *(float4*)&Bs[bk][64 + bn4] = *(const float4*)(bptr + 64 + bn4);
        __syncthreads();
#pragma unroll
        for (int kk = 0; kk < 16; ++kk) {
            float4 aL = *(const float4*)&As[kk][ty * 4];
            float4 aH = *(const float4*)&As[kk][64 + ty * 4];
            float4 bL = *(const float4*)&Bs[kk][tx * 4];
            float4 bH = *(const float4*)&Bs[kk][64 + tx * 4];
            unsigned long long b2[4], a2;
            pack2(b2[0], bL.x, bL.y);
            pack2(b2[1], bL.z, bL.w);
            pack2(b2[2], bH.x, bH.y);
            pack2(b2[3], bH.z, bH.w);
            float ar[8] = {aL.x, aL.y, aL.z, aL.w, aH.x, aH.y, aH.z, aH.w};
#pragma unroll
            for (int i = 0; i < 8; ++i) {
                splat2(a2, ar[i]);
#pragma unroll
                for (int j = 0; j < 4; ++j) ffma2(acc2[i][j], a2, b2[j]);
            }
        }
        __syncthreads();
    }

    // epilogue: per row, in-thread argmax over this thread's 8 columns
    float csq[8];
#pragma unroll
    for (int h = 0; h < 2; ++h)
#pragma unroll
        for (int c = 0; c < 4; ++c)
            csq[4 * h + c] = g_csq[k0 + 64 * h + tx * 4 + c];

#pragma unroll
    for (int q = 0; q < 4; ++q) {
        int mL = ty * 4 + q;               // low-half local row
        unsigned btL = (unsigned)(r0 + mL);
        unsigned long long bestL = 0ull, bestH = 0ull;
        float dotL[8], dotH[8];
#pragma unroll
        for (int jp = 0; jp < 4; ++jp) {
            unpack2(dotL[2 * jp], dotL[2 * jp + 1], acc2[q][jp]);
            unpack2(dotH[2 * jp], dotH[2 * jp + 1], acc2[q + 4][jp]);
        }
#pragma unroll
        for (int c = 0; c < 8; ++c) {
            int k = k0 + ((c < 4) ? (tx * 4 + c) : (64 + tx * 4 + (c - 4)));
            unsigned n = btL * 1024u + (unsigned)k;
            unsigned bb0, bb1;
            tf2x32(fk0, fk1, n, n + HALF_N, bb0, bb1);
            float g0 = gumbel_from_bits(bb0);
            float g1 = gumbel_from_bits(bb1);
            float sL = (2.0f * dotL[c] - csq[c]) * 10.0f + g0;
            float sH = (2.0f * dotH[c] - csq[c]) * 10.0f + g1;
            unsigned long long low = (unsigned long long)(~(unsigned)k);
            unsigned long long cL = ((unsigned long long)fmap(sL) << 32) | low;
            unsigned long long cH = ((unsigned long long)fmap(sH) << 32) | low;
            if (cL > bestL) bestL = cL;
            if (cH > bestH) bestH = cH;
        }
        atomicMax(&sbest[mL], bestL);
        atomicMax(&sbest[64 + mL], bestH);
    }
    __syncthreads();
    if (tid < 128) {
        int r = (tid < 64) ? (r0 + tid) : (8192 + r0 + (tid - 64));
        atomicMax(&g_best[r], sbest[tid]);
    }
}

// ---------------- VQ update: gather, q_out accum, residual, commit loss ----
__global__ void vq_update(const float* __restrict__ cb, int stage) {
    int bt = blockIdx.x;
    int tid = threadIdx.x;  // 128
    unsigned kinv = (unsigned)(g_best[bt] & 0xffffffffull);
    int k = (int)(~kinv);
    float local = 0.0f;
#pragma unroll
    for (int l = 0; l < 4; ++l) {
        int d = tid + 128 * l;
        float r = g_res[bt * DD + d];
        float q = cb[k * DD + d];
        float diff = q - r;
        float qst = r + diff;                     // straight-through value
        float qo = (stage == 0) ? qst : (g_qout[bt * DD + d] + qst);
        g_qout[bt * DD + d] = qo;
        g_res[bt * DD + d] = r - q;
        local += diff * diff;
    }
    __shared__ float red[128];
    red[tid] = local;
    __syncthreads();
    if (tid == 0) g_best[bt] = 0ull;   // reset for next stage (reads done)
    for (int s = 64; s > 0; s >>= 1) {
        if (tid < s) red[tid] += red[tid + s];
        __syncthreads();
    }
    if (tid == 0) atomicAdd(&g_acc[0], red[0]);
}

// ---------------- init: codebook squared norms + zero accumulators ----------
__global__ void vq_init(const float* __restrict__ cb) {
    int k = blockIdx.x;
    int tid = threadIdx.x;  // 128
    float local = 0.0f;
#pragma unroll
    for (int l = 0; l < 4; ++l) {
        float c = cb[k * DD + tid + 128 * l];
        local += c * c;
    }
    __shared__ float red[128];
    red[tid] = local;
    __syncthreads();
    for (int s = 64; s > 0; s >>= 1) {
        if (tid < s) red[tid] += red[tid + s];
        __syncthreads();
    }
    if (tid == 0) g_csq[k] = red[0];
    if (tid < 16) g_best[blockIdx.x * 16 + tid] = 0ull;
    if (blockIdx.x == 0 && tid < 2) g_acc[tid] = 0.0f;
}

__global__ void finalize_k(float* __restrict__ out) {
    out[0] = g_acc[1] * (1.0f / 1638400.0f)      // mse: /(BT*100)
           + g_acc[0] * (1.0f / 67108864.0f);    // commit: /(8 stages * BT * 512)
}

// ---------------- host launcher (graph-capturable, alloc-free) -------------
extern "C" void kernel_launch(void* const* d_in, const int* in_sizes, int n_in,
                              void* d_out, int out_size) {
    const float* x   = (const float*)d_in[0];
    const float* ew1 = (const float*)d_in[1];
    const float* eb1 = (const float*)d_in[2];
    const float* ew2 = (const float*)d_in[3];
    const float* eb2 = (const float*)d_in[4];
    const float* cb  = (const float*)d_in[5];
    const float* dw1 = (const float*)d_in[6];
    const float* db1 = (const float*)d_in[7];
    const float* dw2 = (const float*)d_in[8];
    const float* db2 = (const float*)d_in[9];
    float* out = (float*)d_out;

    float *h1, *res, *qout;
    cudaGetSymbolAddress((void**)&h1,   g_h1);
    cudaGetSymbolAddress((void**)&res,  g_res);
    cudaGetSymbolAddress((void**)&qout, g_qout);

    // fold-in keys for each VQ stage: threefry((0,42),(0,i))
    unsigned fk0[8], fk1[8];
    for (int s = 0; s < 8; ++s) tf2x32(0u, 42u, 0u, (unsigned)s, fk0[s], fk1[s]);

    vq_init<<<KK, 128>>>(cb);
    transpose_cb<<<dim3(KK / 32, DD / 32), dim3(32, 8)>>>(cb);

    // encoder
    conv3<100, 256, false><<<dim3(128, 2), 256>>>(x,  ew1, eb1, h1,  nullptr);
    conv3<256, 512, false><<<dim3(128, 4), 256>>>(h1, ew2, eb2, res, nullptr);

    // residual VQ, 8 stages
    for (int s = 0; s < 8; ++s) {
        vq_score<<<dim3(128, 8), 256>>>(fk0[s], fk1[s]);
        vq_update<<<BT, 128>>>(cb, s);
    }

    // decoder (+ fused MSE on the last conv)
    conv3<512, 256, false><<<dim3(128, 2), 256>>>(qout, dw1, db1, h1, nullptr);
    conv3<256, 100, true ><<<dim3(128, 1), 256>>>(h1,  dw2, db2, nullptr, x);

    finalize_k<<<1, 1>>>(out);
}